// round 5
// baseline (speedup 1.0000x reference)
#include <cuda_runtime.h>

#define B_  4
#define N_  2048
#define H_  16
#define DM_ 1024
#define DK_ 64
#define BN_ (B_*N_)          // 8192

// ---------------- scratch (device globals; no allocation allowed) ----------
__device__ unsigned g_x[3][BN_*DM_];     // tf32 inputs (Q,K,V), row-major [bn][d]
__device__ unsigned g_w[3][DM_*DM_];     // tf32 proj weights, layout [k][h*64+j]
__device__ unsigned g_wo[DM_*DM_];       // tf32 Wo, [k][n]
__device__ unsigned g_q[B_*H_*N_*DK_];   // tf32, [b,h,n,dk] (pre-scaled by 0.125)
__device__ unsigned g_k[B_*H_*N_*DK_];
__device__ unsigned g_v[B_*H_*N_*DK_];
__device__ unsigned g_att[BN_*DM_];      // tf32 attention output [bn][h*dv]

__device__ __forceinline__ unsigned f2tf(float x) {
    unsigned r;
    asm("cvt.rna.tf32.f32 %0, %1;" : "=r"(r) : "f"(x));
    return r;
}

__device__ __forceinline__ void mma_tf32(float c[4],
    unsigned a0, unsigned a1, unsigned a2, unsigned a3,
    unsigned b0, unsigned b1)
{
    asm("mma.sync.aligned.m16n8k8.row.col.f32.tf32.tf32.f32 "
        "{%0,%1,%2,%3},{%4,%5,%6,%7},{%8,%9},{%0,%1,%2,%3};"
        : "+f"(c[0]), "+f"(c[1]), "+f"(c[2]), "+f"(c[3])
        : "r"(a0), "r"(a1), "r"(a2), "r"(a3), "r"(b0), "r"(b1));
}

__device__ __forceinline__ void cp16(unsigned d, const void* s) {
    asm volatile("cp.async.cg.shared.global [%0], [%1], 16;" :: "r"(d), "l"(s));
}
__device__ __forceinline__ void cp_commit() { asm volatile("cp.async.commit_group;"); }
__device__ __forceinline__ void cp_wait1()  { asm volatile("cp.async.wait_group 1;"); }
__device__ __forceinline__ void cp_wait0()  { asm volatile("cp.async.wait_group 0;"); }

// ---------------------------------------------------------------------------
// Conversion kernels (fp32 -> tf32 bits)
// ---------------------------------------------------------------------------
__global__ void cvt_in_kernel(const float* __restrict__ Q,
                              const float* __restrict__ K,
                              const float* __restrict__ V)
{
    const float* src = (blockIdx.y == 0) ? Q : (blockIdx.y == 1) ? K : V;
    unsigned* dst = g_x[blockIdx.y];
    int i = blockIdx.x * 256 + threadIdx.x;
    float4 v = ((const float4*)src)[i];
    uint4 u;
    u.x = f2tf(v.x); u.y = f2tf(v.y); u.z = f2tf(v.z); u.w = f2tf(v.w);
    ((uint4*)dst)[i] = u;
}

__global__ void cvt_w_kernel(const float* __restrict__ Wq,
                             const float* __restrict__ Wk,
                             const float* __restrict__ Wv)
{
    const float* w = (blockIdx.y == 0) ? Wq : (blockIdx.y == 1) ? Wk : Wv;
    unsigned* dst = g_w[blockIdx.y];
    int i = blockIdx.x * 256 + threadIdx.x;
    int k = i >> 10, c = i & 1023;
    int h = c >> 6, j = c & 63;
    dst[i] = f2tf(w[(h << 16) + (k << 6) + j]);       // [h][k][j] -> [k][h*64+j]
}

__global__ void cvt_wo_kernel(const float* __restrict__ Wo)
{
    int i = blockIdx.x * 256 + threadIdx.x;
    float4 v = ((const float4*)Wo)[i];
    uint4 u;
    u.x = f2tf(v.x); u.y = f2tf(v.y); u.z = f2tf(v.z); u.w = f2tf(v.w);
    ((uint4*)g_wo)[i] = u;
}

// ---------------------------------------------------------------------------
// 128x128 tf32 GEMM, BK=32, 8 warps (32x64 warp tiles), cp.async 2-stage.
// ---------------------------------------------------------------------------
#define AST 4608                    // 128*36 words per A stage
#define BST 4352                    // 32*136 words per B stage
#define GEMM_SMEM ((AST + BST) * 2 * 4)

struct GemmAcc { float a[2][8][4]; };

__device__ __forceinline__ void gemm_mainloop(
    const unsigned* __restrict__ A,     // block-row base, ld = DM_
    const unsigned* __restrict__ Bw,    // col-slice base, ld = DM_
    unsigned* sA, unsigned* sB, GemmAcc& acc)
{
    const int tid  = threadIdx.x;
    const int wid  = tid >> 5, lane = tid & 31;
    const int g    = lane >> 2, tig = lane & 3;
    const int wm   = wid & 3;          // 0..3 -> rows wm*32
    const int wn   = wid >> 2;         // 0..1 -> cols wn*64

#pragma unroll
    for (int mt = 0; mt < 2; ++mt)
#pragma unroll
        for (int nt = 0; nt < 8; ++nt)
#pragma unroll
            for (int i = 0; i < 4; ++i) acc.a[mt][nt][i] = 0.f;

    // prologue: stage 0
    {
        unsigned ab = (unsigned)__cvta_generic_to_shared(sA);
        unsigned bb = (unsigned)__cvta_generic_to_shared(sB);
#pragma unroll
        for (int t = 0; t < 4; ++t) {
            int ca = tid + t * 256;
            int row = ca >> 3, cc = ca & 7;
            cp16(ab + (row * 36 + cc * 4) * 4, A + (size_t)row * DM_ + cc * 4);
        }
#pragma unroll
        for (int t = 0; t < 4; ++t) {
            int cb = tid + t * 256;
            int kk = cb >> 5, cc = cb & 31;
            cp16(bb + (kk * 136 + cc * 4) * 4, Bw + (size_t)kk * DM_ + cc * 4);
        }
        cp_commit();
    }

    for (int kt = 0; kt < 32; ++kt) {
        int s = kt & 1;
        if (kt < 31) {
            int k0 = (kt + 1) * 32;
            unsigned ab = (unsigned)__cvta_generic_to_shared(sA + (s ^ 1) * AST);
            unsigned bb = (unsigned)__cvta_generic_to_shared(sB + (s ^ 1) * BST);
#pragma unroll
            for (int t = 0; t < 4; ++t) {
                int ca = tid + t * 256;
                int row = ca >> 3, cc = ca & 7;
                cp16(ab + (row * 36 + cc * 4) * 4, A + (size_t)row * DM_ + k0 + cc * 4);
            }
#pragma unroll
            for (int t = 0; t < 4; ++t) {
                int cb = tid + t * 256;
                int kk = cb >> 5, cc = cb & 31;
                cp16(bb + (kk * 136 + cc * 4) * 4, Bw + (size_t)(k0 + kk) * DM_ + cc * 4);
            }
            cp_commit();
            cp_wait1();
        } else {
            cp_wait0();
        }
        __syncthreads();

        const unsigned* cA = sA + s * AST;
        const unsigned* cB = sB + s * BST;
#pragma unroll
        for (int ks = 0; ks < 4; ++ks) {
            int kb = ks * 8;
            unsigned a[2][4], bf[8][2];
#pragma unroll
            for (int mt = 0; mt < 2; ++mt) {
                int r0 = wm * 32 + mt * 16;
                a[mt][0] = cA[(r0 + g) * 36 + kb + tig];
                a[mt][1] = cA[(r0 + 8 + g) * 36 + kb + tig];
                a[mt][2] = cA[(r0 + g) * 36 + kb + tig + 4];
                a[mt][3] = cA[(r0 + 8 + g) * 36 + kb + tig + 4];
            }
#pragma unroll
            for (int nt = 0; nt < 8; ++nt) {
                int n0 = wn * 64 + nt * 8;
                bf[nt][0] = cB[(kb + tig) * 136 + n0 + g];
                bf[nt][1] = cB[(kb + tig + 4) * 136 + n0 + g];
            }
#pragma unroll
            for (int mt = 0; mt < 2; ++mt)
#pragma unroll
                for (int nt = 0; nt < 8; ++nt)
                    mma_tf32(acc.a[mt][nt], a[mt][0], a[mt][1], a[mt][2], a[mt][3],
                             bf[nt][0], bf[nt][1]);
        }
        __syncthreads();
    }
}

// ---------------------------------------------------------------------------
// Projections: grid (8, 64, 3), 256 threads. C -> g_q/g_k/g_v as tf32.
// ---------------------------------------------------------------------------
__global__ __launch_bounds__(256, 2) void proj_gemm(
    const float* __restrict__ bq, const float* __restrict__ bk,
    const float* __restrict__ bv)
{
    extern __shared__ unsigned sm[];
    unsigned* sA = sm;
    unsigned* sB = sm + 2 * AST;

    const int op = blockIdx.z;
    const unsigned* A  = g_x[op] + (size_t)blockIdx.y * 128 * DM_;
    const unsigned* Bw = g_w[op] + blockIdx.x * 128;
    const float* bias  = (op == 0) ? bq : (op == 1) ? bk : bv;
    unsigned* dst      = (op == 0) ? g_q : (op == 1) ? g_k : g_v;
    const float scale  = (op == 0) ? 0.125f : 1.f;

    GemmAcc acc;
    gemm_mainloop(A, Bw, sA, sB, acc);

    const int tid = threadIdx.x, wid = tid >> 5, lane = tid & 31;
    const int g = lane >> 2, tig = lane & 3;
    const int wm = wid & 3, wn = wid >> 2;

#pragma unroll
    for (int mt = 0; mt < 2; ++mt) {
#pragma unroll
        for (int nt = 0; nt < 8; ++nt) {
#pragma unroll
            for (int half = 0; half < 2; ++half) {
                int r  = wm * 32 + mt * 16 + half * 8 + g;
                int c  = wn * 64 + nt * 8 + tig * 2;
                int rg = blockIdx.y * 128 + r;
                int cg = blockIdx.x * 128 + c;
                int b  = rg >> 11, n = rg & 2047;
                int h  = cg >> 6,  j = cg & 63;
                float v0 = (acc.a[mt][nt][half * 2 + 0] + bias[cg]) * scale;
                float v1 = (acc.a[mt][nt][half * 2 + 1] + bias[cg + 1]) * scale;
                uint2 u; u.x = f2tf(v0); u.y = f2tf(v1);
                *(uint2*)&dst[(size_t)(((b << 4) | h) * N_ + n) * DK_ + j] = u;
            }
        }
    }
}

// ---------------------------------------------------------------------------
// Output projection: grid (8, 64), 256 threads. C -> fp32 out.
// ---------------------------------------------------------------------------
__global__ __launch_bounds__(256, 2) void outproj_gemm(
    const float* __restrict__ bo, float* __restrict__ out)
{
    extern __shared__ unsigned sm[];
    unsigned* sA = sm;
    unsigned* sB = sm + 2 * AST;

    const unsigned* A  = g_att + (size_t)blockIdx.y * 128 * DM_;
    const unsigned* Bw = g_wo + blockIdx.x * 128;

    GemmAcc acc;
    gemm_mainloop(A, Bw, sA, sB, acc);

    const int tid = threadIdx.x, wid = tid >> 5, lane = tid & 31;
    const int g = lane >> 2, tig = lane & 3;
    const int wm = wid & 3, wn = wid >> 2;

#pragma unroll
    for (int mt = 0; mt < 2; ++mt) {
#pragma unroll
        for (int nt = 0; nt < 8; ++nt) {
#pragma unroll
            for (int half = 0; half < 2; ++half) {
                int r  = wm * 32 + mt * 16 + half * 8 + g;
                int c  = wn * 64 + nt * 8 + tig * 2;
                int rg = blockIdx.y * 128 + r;
                int cg = blockIdx.x * 128 + c;
                float2 v;
                v.x = acc.a[mt][nt][half * 2 + 0] + bo[cg];
                v.y = acc.a[mt][nt][half * 2 + 1] + bo[cg + 1];
                *(float2*)(out + (size_t)rg * DM_ + cg) = v;
            }
        }
    }
}

// ---------------------------------------------------------------------------
// Flash attention: grid (16, 16, 4), 256 threads (8 warps x 16 q-rows).
// Q fragments in registers; K/V double-buffered via cp.async; tf32 mma.
// ---------------------------------------------------------------------------
#define KST (64*68)     // K stage words
#define VST (64*72)     // V stage words
#define FL_SMEM ((2*KST + 2*VST + 128*68) * 4)   // 106.5 KB

__global__ __launch_bounds__(256, 1) void flash_kernel(const int* __restrict__ mask_ptr)
{
    extern __shared__ unsigned sm[];
    unsigned* sK = sm;                        // [2][64][68]
    unsigned* sV = sm + 2 * KST;              // [2][64][72]
    unsigned* sP = sm + 2 * KST + 2 * VST;    // [128][68]

    const int tid = threadIdx.x, wid = tid >> 5, lane = tid & 31;
    const int g = lane >> 2, tig = lane & 3;
    const int qt = blockIdx.x, h = blockIdx.y, b = blockIdx.z;
    const int bh = b * H_ + h;
    const unsigned* qb = g_q + (size_t)bh * N_ * DK_;
    const unsigned* kb = g_k + (size_t)bh * N_ * DK_;
    const unsigned* vb = g_v + (size_t)bh * N_ * DK_;
    const int w16 = wid * 16;

    const unsigned skb = (unsigned)__cvta_generic_to_shared(sK);
    const unsigned svb = (unsigned)__cvta_generic_to_shared(sV);

    const int msk = *mask_ptr;
    const int kt_end = msk ? (2 * qt + 1) : (N_ / 64 - 1);

    // Stage Q tile (128x64) into sP
#pragma unroll
    for (int t = 0; t < 8; ++t) {
        int idx = tid + t * 256;
        int row = idx >> 4, c4 = (idx & 15) << 2;
        *(uint4*)&sP[row * 68 + c4] =
            *(const uint4*)(qb + (size_t)(qt * 128 + row) * DK_ + c4);
    }
    __syncthreads();

    // Issue K/V tile 0 loads (overlap with Q fragment extraction)
    {
#pragma unroll
        for (int t = 0; t < 4; ++t) {
            int idx = tid + t * 256;
            int row = idx >> 4, c4 = (idx & 15) << 2;
            cp16(skb + (row * 68 + c4) * 4, kb + (size_t)row * DK_ + c4);
            cp16(svb + (row * 72 + c4) * 4, vb + (size_t)row * DK_ + c4);
        }
        cp_commit();
    }

    // Q fragments -> registers
    unsigned q[8][4];
#pragma unroll
    for (int ks = 0; ks < 8; ++ks) {
        int kb8 = ks * 8;
        q[ks][0] = sP[(w16 + g) * 68 + kb8 + tig];
        q[ks][1] = sP[(w16 + 8 + g) * 68 + kb8 + tig];
        q[ks][2] = sP[(w16 + g) * 68 + kb8 + tig + 4];
        q[ks][3] = sP[(w16 + 8 + g) * 68 + kb8 + tig + 4];
    }

    float m0 = -1e30f, m1 = -1e30f, l0 = 0.f, l1 = 0.f;
    float o[8][4];
#pragma unroll
    for (int nt = 0; nt < 8; ++nt)
#pragma unroll
        for (int i = 0; i < 4; ++i) o[nt][i] = 0.f;

    for (int kt = 0; kt <= kt_end; ++kt) {
        int s = kt & 1;
        if (kt < kt_end) {
            const unsigned* kn = kb + (size_t)(kt + 1) * 64 * DK_;
            const unsigned* vn = vb + (size_t)(kt + 1) * 64 * DK_;
            unsigned ka = skb + (s ^ 1) * KST * 4;
            unsigned va = svb + (s ^ 1) * VST * 4;
#pragma unroll
            for (int t = 0; t < 4; ++t) {
                int idx = tid + t * 256;
                int row = idx >> 4, c4 = (idx & 15) << 2;
                cp16(ka + (row * 68 + c4) * 4, kn + (size_t)row * DK_ + c4);
                cp16(va + (row * 72 + c4) * 4, vn + (size_t)row * DK_ + c4);
            }
            cp_commit();
            cp_wait1();
        } else {
            cp_wait0();
        }
        __syncthreads();

        const unsigned* cK = sK + s * KST;
        const unsigned* cV = sV + s * VST;

        // S = Q * K^T  (16x64 per warp)
        float sc[8][4];
#pragma unroll
        for (int nt = 0; nt < 8; ++nt)
#pragma unroll
            for (int i = 0; i < 4; ++i) sc[nt][i] = 0.f;

#pragma unroll
        for (int ks = 0; ks < 8; ++ks) {
            int kb8 = ks * 8;
#pragma unroll
            for (int nt = 0; nt < 8; ++nt) {
                int n0 = nt * 8;
                unsigned b0 = cK[(n0 + g) * 68 + kb8 + tig];
                unsigned b1 = cK[(n0 + g) * 68 + kb8 + tig + 4];
                mma_tf32(sc[nt], q[ks][0], q[ks][1], q[ks][2], q[ks][3], b0, b1);
            }
        }

        // Causal mask (partial tiles only)
        if (msk && kt >= 2 * qt) {
            int ra = qt * 128 + w16 + g;
            int rb = ra + 8;
#pragma unroll
            for (int nt = 0; nt < 8; ++nt) {
                int c0 = kt * 64 + nt * 8 + tig * 2, c1 = c0 + 1;
                if (c0 > ra) sc[nt][0] = -1e30f;
                if (c1 > ra) sc[nt][1] = -1e30f;
                if (c0 > rb) sc[nt][2] = -1e30f;
                if (c1 > rb) sc[nt][3] = -1e30f;
            }
        }

        // Online softmax + P -> sP (tf32)
        {
            float mxa = -1e30f, mxb = -1e30f;
#pragma unroll
            for (int nt = 0; nt < 8; ++nt) {
                mxa = fmaxf(mxa, fmaxf(sc[nt][0], sc[nt][1]));
                mxb = fmaxf(mxb, fmaxf(sc[nt][2], sc[nt][3]));
            }
#pragma unroll
            for (int off = 1; off < 4; off <<= 1) {
                mxa = fmaxf(mxa, __shfl_xor_sync(0xffffffffu, mxa, off));
                mxb = fmaxf(mxb, __shfl_xor_sync(0xffffffffu, mxb, off));
            }
            float mna = fmaxf(m0, mxa), mnb = fmaxf(m1, mxb);
            float ala = __expf(m0 - mna), alb = __expf(m1 - mnb);
            float sa = 0.f, sb = 0.f;
#pragma unroll
            for (int nt = 0; nt < 8; ++nt) {
                float p0 = __expf(sc[nt][0] - mna);
                float p1 = __expf(sc[nt][1] - mna);
                float p2 = __expf(sc[nt][2] - mnb);
                float p3 = __expf(sc[nt][3] - mnb);
                sa += p0 + p1; sb += p2 + p3;
                uint2 ua; ua.x = f2tf(p0); ua.y = f2tf(p1);
                uint2 ub; ub.x = f2tf(p2); ub.y = f2tf(p3);
                *(uint2*)&sP[(w16 + g) * 68 + nt * 8 + tig * 2]     = ua;
                *(uint2*)&sP[(w16 + 8 + g) * 68 + nt * 8 + tig * 2] = ub;
            }
#pragma unroll
            for (int off = 1; off < 4; off <<= 1) {
                sa += __shfl_xor_sync(0xffffffffu, sa, off);
                sb += __shfl_xor_sync(0xffffffffu, sb, off);
            }
            l0 = l0 * ala + sa; m0 = mna;
            l1 = l1 * alb + sb; m1 = mnb;
#pragma unroll
            for (int nt = 0; nt < 8; ++nt) {
                o[nt][0] *= ala; o[nt][1] *= ala;
                o[nt][2] *= alb; o[nt][3] *= alb;
            }
        }
        __syncwarp();   // warp's own sP rows only

        // O += P * V  (16x64 per warp)
#pragma unroll
        for (int ks = 0; ks < 8; ++ks) {
            int kb8 = ks * 8;
            unsigned pa0 = sP[(w16 + g) * 68 + kb8 + tig];
            unsigned pa1 = sP[(w16 + 8 + g) * 68 + kb8 + tig];
            unsigned pa2 = sP[(w16 + g) * 68 + kb8 + tig + 4];
            unsigned pa3 = sP[(w16 + 8 + g) * 68 + kb8 + tig + 4];
#pragma unroll
            for (int nt = 0; nt < 8; ++nt) {
                int n0 = nt * 8;
                unsigned b0 = cV[(kb8 + tig) * 72 + n0 + g];
                unsigned b1 = cV[(kb8 + tig + 4) * 72 + n0 + g];
                mma_tf32(o[nt], pa0, pa1, pa2, pa3, b0, b1);
            }
        }
        __syncthreads();   // all warps done with buffer s before it is refilled
    }

    // Normalize + write tf32 to g_att [bn][h*64+col]
    float ia = 1.f / l0, ib = 1.f / l1;
    int na = qt * 128 + w16 + g;
    int nb = na + 8;
#pragma unroll
    for (int nt = 0; nt < 8; ++nt) {
        int col = h * 64 + nt * 8 + tig * 2;
        uint2 ua, ub;
        ua.x = f2tf(o[nt][0] * ia); ua.y = f2tf(o[nt][1] * ia);
        ub.x = f2tf(o[nt][2] * ib); ub.y = f2tf(o[nt][3] * ib);
        *(uint2*)&g_att[(size_t)(b * N_ + na) * DM_ + col] = ua;
        *(uint2*)&g_att[(size_t)(b * N_ + nb) * DM_ + col] = ub;
    }
}

// ---------------------------------------------------------------------------
extern "C" void kernel_launch(void* const* d_in, const int* in_sizes, int n_in,
                              void* d_out, int out_size)
{
    const float* Q  = (const float*)d_in[0];
    const float* K  = (const float*)d_in[1];
    const float* V  = (const float*)d_in[2];
    const float* Wq = (const float*)d_in[3];
    const float* bq = (const float*)d_in[4];
    const float* Wk = (const float*)d_in[5];
    const float* bk = (const float*)d_in[6];
    const float* Wv = (const float*)d_in[7];
    const float* bv = (const float*)d_in[8];
    const float* Wo = (const float*)d_in[9];
    const float* bo = (const float*)d_in[10];
    const int*  msk = (const int*)d_in[11];
    float* out = (float*)d_out;

    cudaFuncSetAttribute(proj_gemm,    cudaFuncAttributeMaxDynamicSharedMemorySize, GEMM_SMEM);
    cudaFuncSetAttribute(outproj_gemm, cudaFuncAttributeMaxDynamicSharedMemorySize, GEMM_SMEM);
    cudaFuncSetAttribute(flash_kernel, cudaFuncAttributeMaxDynamicSharedMemorySize, FL_SMEM);

    cvt_in_kernel<<<dim3(8192, 3), 256>>>(Q, K, V);
    cvt_w_kernel<<<dim3(4096, 3), 256>>>(Wq, Wk, Wv);
    cvt_wo_kernel<<<1024, 256>>>(Wo);
    proj_gemm<<<dim3(8, 64, 3), 256, GEMM_SMEM>>>(bq, bk, bv);
    flash_kernel<<<dim3(16, H_, B_), 256, FL_SMEM>>>(msk);
    outproj_gemm<<<dim3(8, 64), 256, GEMM_SMEM>>>(bo, out);
}

// round 7
// speedup vs baseline: 1.0887x; 1.0887x over previous
#include <cuda_runtime.h>

#define B_  4
#define N_  2048
#define H_  16
#define DM_ 1024
#define DK_ 64
#define BN_ (B_*N_)          // 8192

// ---------------- scratch (device globals; no allocation allowed) ----------
__device__ unsigned g_w[3][DM_*DM_];     // tf32 proj weights, layout [k][h*64+j]
__device__ unsigned g_wo[DM_*DM_];       // tf32 Wo, [k][n]
__device__ unsigned g_q[B_*H_*N_*DK_];   // tf32, [b,h,n,dk] (pre-scaled by 0.125)
__device__ unsigned g_k[B_*H_*N_*DK_];
__device__ unsigned g_v[B_*H_*N_*DK_];
__device__ unsigned g_att[BN_*DM_];      // tf32 attention output [bn][h*dv]

__device__ __forceinline__ unsigned f2tf(float x) {
    unsigned r;
    asm("cvt.rna.tf32.f32 %0, %1;" : "=r"(r) : "f"(x));
    return r;
}

__device__ __forceinline__ void mma_tf32(float c[4],
    unsigned a0, unsigned a1, unsigned a2, unsigned a3,
    unsigned b0, unsigned b1)
{
    asm("mma.sync.aligned.m16n8k8.row.col.f32.tf32.tf32.f32 "
        "{%0,%1,%2,%3},{%4,%5,%6,%7},{%8,%9},{%0,%1,%2,%3};"
        : "+f"(c[0]), "+f"(c[1]), "+f"(c[2]), "+f"(c[3])
        : "r"(a0), "r"(a1), "r"(a2), "r"(a3), "r"(b0), "r"(b1));
}

__device__ __forceinline__ void cp16(unsigned d, const void* s) {
    asm volatile("cp.async.cg.shared.global [%0], [%1], 16;" :: "r"(d), "l"(s));
}
__device__ __forceinline__ void cp_commit() { asm volatile("cp.async.commit_group;"); }
__device__ __forceinline__ void cp_wait1()  { asm volatile("cp.async.wait_group 1;"); }
__device__ __forceinline__ void cp_wait0()  { asm volatile("cp.async.wait_group 0;"); }

// ---------------------------------------------------------------------------
// Weight conversion kernels (fp32 -> tf32 bits)
// ---------------------------------------------------------------------------
__global__ void cvt_w_kernel(const float* __restrict__ Wq,
                             const float* __restrict__ Wk,
                             const float* __restrict__ Wv)
{
    const float* w = (blockIdx.y == 0) ? Wq : (blockIdx.y == 1) ? Wk : Wv;
    unsigned* dst = g_w[blockIdx.y];
    int i = blockIdx.x * 256 + threadIdx.x;
    int k = i >> 10, c = i & 1023;
    int h = c >> 6, j = c & 63;
    dst[i] = f2tf(w[(h << 16) + (k << 6) + j]);       // [h][k][j] -> [k][h*64+j]
}

__global__ void cvt_wo_kernel(const float* __restrict__ Wo)
{
    int i = blockIdx.x * 256 + threadIdx.x;
    float4 v = ((const float4*)Wo)[i];
    uint4 u;
    u.x = f2tf(v.x); u.y = f2tf(v.y); u.z = f2tf(v.z); u.w = f2tf(v.w);
    ((uint4*)g_wo)[i] = u;
}

// ---------------------------------------------------------------------------
// 128x128 tf32 GEMM, BK=32, 8 warps (32x64 warp tiles), cp.async 2-stage.
// CVTA: A is raw fp32, converted to tf32 at fragment load.
// ---------------------------------------------------------------------------
#define AST 4608                    // 128*36 words per A stage
#define BST 4352                    // 32*136 words per B stage
#define GEMM_SMEM ((AST + BST) * 2 * 4)

struct GemmAcc { float a[2][8][4]; };

template<bool CVTA>
__device__ __forceinline__ void gemm_mainloop(
    const unsigned* __restrict__ A,     // block-row base, ld = DM_
    const unsigned* __restrict__ Bw,    // col-slice base, ld = DM_
    unsigned* sA, unsigned* sB, GemmAcc& acc)
{
    const int tid  = threadIdx.x;
    const int wid  = tid >> 5, lane = tid & 31;
    const int g    = lane >> 2, tig = lane & 3;
    const int wm   = wid & 3;          // 0..3 -> rows wm*32
    const int wn   = wid >> 2;         // 0..1 -> cols wn*64

#pragma unroll
    for (int mt = 0; mt < 2; ++mt)
#pragma unroll
        for (int nt = 0; nt < 8; ++nt)
#pragma unroll
            for (int i = 0; i < 4; ++i) acc.a[mt][nt][i] = 0.f;

    // prologue: stage 0
    {
        unsigned ab = (unsigned)__cvta_generic_to_shared(sA);
        unsigned bb = (unsigned)__cvta_generic_to_shared(sB);
#pragma unroll
        for (int t = 0; t < 4; ++t) {
            int ca = tid + t * 256;
            int row = ca >> 3, cc = ca & 7;
            cp16(ab + (row * 36 + cc * 4) * 4, A + (size_t)row * DM_ + cc * 4);
        }
#pragma unroll
        for (int t = 0; t < 4; ++t) {
            int cb = tid + t * 256;
            int kk = cb >> 5, cc = cb & 31;
            cp16(bb + (kk * 136 + cc * 4) * 4, Bw + (size_t)kk * DM_ + cc * 4);
        }
        cp_commit();
    }

    for (int kt = 0; kt < 32; ++kt) {
        int s = kt & 1;
        if (kt < 31) {
            int k0 = (kt + 1) * 32;
            unsigned ab = (unsigned)__cvta_generic_to_shared(sA + (s ^ 1) * AST);
            unsigned bb = (unsigned)__cvta_generic_to_shared(sB + (s ^ 1) * BST);
#pragma unroll
            for (int t = 0; t < 4; ++t) {
                int ca = tid + t * 256;
                int row = ca >> 3, cc = ca & 7;
                cp16(ab + (row * 36 + cc * 4) * 4, A + (size_t)row * DM_ + k0 + cc * 4);
            }
#pragma unroll
            for (int t = 0; t < 4; ++t) {
                int cb = tid + t * 256;
                int kk = cb >> 5, cc = cb & 31;
                cp16(bb + (kk * 136 + cc * 4) * 4, Bw + (size_t)(k0 + kk) * DM_ + cc * 4);
            }
            cp_commit();
            cp_wait1();
        } else {
            cp_wait0();
        }
        __syncthreads();

        const unsigned* cA = sA + s * AST;
        const unsigned* cB = sB + s * BST;
#pragma unroll
        for (int ks = 0; ks < 4; ++ks) {
            int kb = ks * 8;
            unsigned a[2][4], bf[8][2];
#pragma unroll
            for (int mt = 0; mt < 2; ++mt) {
                int r0 = wm * 32 + mt * 16;
                unsigned r0v = cA[(r0 + g) * 36 + kb + tig];
                unsigned r1v = cA[(r0 + 8 + g) * 36 + kb + tig];
                unsigned r2v = cA[(r0 + g) * 36 + kb + tig + 4];
                unsigned r3v = cA[(r0 + 8 + g) * 36 + kb + tig + 4];
                if (CVTA) {
                    a[mt][0] = f2tf(__uint_as_float(r0v));
                    a[mt][1] = f2tf(__uint_as_float(r1v));
                    a[mt][2] = f2tf(__uint_as_float(r2v));
                    a[mt][3] = f2tf(__uint_as_float(r3v));
                } else {
                    a[mt][0] = r0v; a[mt][1] = r1v; a[mt][2] = r2v; a[mt][3] = r3v;
                }
            }
#pragma unroll
            for (int nt = 0; nt < 8; ++nt) {
                int n0 = wn * 64 + nt * 8;
                bf[nt][0] = cB[(kb + tig) * 136 + n0 + g];
                bf[nt][1] = cB[(kb + tig + 4) * 136 + n0 + g];
            }
#pragma unroll
            for (int mt = 0; mt < 2; ++mt)
#pragma unroll
                for (int nt = 0; nt < 8; ++nt)
                    mma_tf32(acc.a[mt][nt], a[mt][0], a[mt][1], a[mt][2], a[mt][3],
                             bf[nt][0], bf[nt][1]);
        }
        __syncthreads();
    }
}

// ---------------------------------------------------------------------------
// Projections: grid (8, 64, 3), 256 threads. Raw fp32 A inputs. C -> tf32.
// ---------------------------------------------------------------------------
__global__ __launch_bounds__(256, 2) void proj_gemm(
    const float* __restrict__ Qp, const float* __restrict__ Kp,
    const float* __restrict__ Vp,
    const float* __restrict__ bq, const float* __restrict__ bk,
    const float* __restrict__ bv)
{
    extern __shared__ unsigned sm[];
    unsigned* sA = sm;
    unsigned* sB = sm + 2 * AST;

    const int op = blockIdx.z;
    const float* Xp = (op == 0) ? Qp : (op == 1) ? Kp : Vp;
    const unsigned* A  = (const unsigned*)Xp + (size_t)blockIdx.y * 128 * DM_;
    const unsigned* Bw = g_w[op] + blockIdx.x * 128;
    const float* bias  = (op == 0) ? bq : (op == 1) ? bk : bv;
    unsigned* dst      = (op == 0) ? g_q : (op == 1) ? g_k : g_v;
    const float scale  = (op == 0) ? 0.125f : 1.f;

    GemmAcc acc;
    gemm_mainloop<true>(A, Bw, sA, sB, acc);

    const int tid = threadIdx.x, wid = tid >> 5, lane = tid & 31;
    const int g = lane >> 2, tig = lane & 3;
    const int wm = wid & 3, wn = wid >> 2;

#pragma unroll
    for (int mt = 0; mt < 2; ++mt) {
#pragma unroll
        for (int nt = 0; nt < 8; ++nt) {
#pragma unroll
            for (int half = 0; half < 2; ++half) {
                int r  = wm * 32 + mt * 16 + half * 8 + g;
                int c  = wn * 64 + nt * 8 + tig * 2;
                int rg = blockIdx.y * 128 + r;
                int cg = blockIdx.x * 128 + c;
                int b  = rg >> 11, n = rg & 2047;
                int h  = cg >> 6,  j = cg & 63;
                float v0 = (acc.a[mt][nt][half * 2 + 0] + bias[cg]) * scale;
                float v1 = (acc.a[mt][nt][half * 2 + 1] + bias[cg + 1]) * scale;
                uint2 u; u.x = f2tf(v0); u.y = f2tf(v1);
                *(uint2*)&dst[(size_t)(((b << 4) | h) * N_ + n) * DK_ + j] = u;
            }
        }
    }
}

// ---------------------------------------------------------------------------
// Output projection: grid (8, 64), 256 threads. C -> fp32 out.
// ---------------------------------------------------------------------------
__global__ __launch_bounds__(256, 2) void outproj_gemm(
    const float* __restrict__ bo, float* __restrict__ out)
{
    extern __shared__ unsigned sm[];
    unsigned* sA = sm;
    unsigned* sB = sm + 2 * AST;

    const unsigned* A  = g_att + (size_t)blockIdx.y * 128 * DM_;
    const unsigned* Bw = g_wo + blockIdx.x * 128;

    GemmAcc acc;
    gemm_mainloop<false>(A, Bw, sA, sB, acc);

    const int tid = threadIdx.x, wid = tid >> 5, lane = tid & 31;
    const int g = lane >> 2, tig = lane & 3;
    const int wm = wid & 3, wn = wid >> 2;

#pragma unroll
    for (int mt = 0; mt < 2; ++mt) {
#pragma unroll
        for (int nt = 0; nt < 8; ++nt) {
#pragma unroll
            for (int half = 0; half < 2; ++half) {
                int r  = wm * 32 + mt * 16 + half * 8 + g;
                int c  = wn * 64 + nt * 8 + tig * 2;
                int rg = blockIdx.y * 128 + r;
                int cg = blockIdx.x * 128 + c;
                float2 v;
                v.x = acc.a[mt][nt][half * 2 + 0] + bo[cg];
                v.y = acc.a[mt][nt][half * 2 + 1] + bo[cg + 1];
                *(float2*)(out + (size_t)rg * DM_ + cg) = v;
            }
        }
    }
}

// ---------------------------------------------------------------------------
// Flash attention: grid (8, 16, 4), 256 threads (8 warps x 16 q-rows).
// Causal work pairing: CTA bx handles q-tiles {bx, 15-bx} -> uniform 34 tiles.
// 2 CTAs/SM (smem 106.5KB x2 fits in 227KB carveout).
// ---------------------------------------------------------------------------
#define KST (64*68)     // K stage words
#define VST (64*72)     // V stage words
#define FL_SMEM ((2*KST + 2*VST + 128*68) * 4)   // 106.5 KB

__global__ __launch_bounds__(256, 2) void flash_kernel(const int* __restrict__ mask_ptr)
{
    extern __shared__ unsigned sm[];
    unsigned* sK = sm;                        // [2][64][68]
    unsigned* sV = sm + 2 * KST;              // [2][64][72]
    unsigned* sP = sm + 2 * KST + 2 * VST;    // [128][68]

    const int tid = threadIdx.x, wid = tid >> 5, lane = tid & 31;
    const int g = lane >> 2, tig = lane & 3;
    const int bx = blockIdx.x, h = blockIdx.y, b = blockIdx.z;
    const int bh = b * H_ + h;
    const unsigned* qb = g_q + (size_t)bh * N_ * DK_;
    const unsigned* kb = g_k + (size_t)bh * N_ * DK_;
    const unsigned* vb = g_v + (size_t)bh * N_ * DK_;
    const int w16 = wid * 16;

    const unsigned skb = (unsigned)__cvta_generic_to_shared(sK);
    const unsigned svb = (unsigned)__cvta_generic_to_shared(sV);

    const int msk = *mask_ptr;

    for (int pass = 0; pass < 2; ++pass) {
        const int qt = pass ? (15 - bx) : bx;
        const int kt_end = msk ? (2 * qt + 1) : (N_ / 64 - 1);

        // Stage Q tile (128x64) into sP
#pragma unroll
        for (int t = 0; t < 8; ++t) {
            int idx = tid + t * 256;
            int row = idx >> 4, c4 = (idx & 15) << 2;
            *(uint4*)&sP[row * 68 + c4] =
                *(const uint4*)(qb + (size_t)(qt * 128 + row) * DK_ + c4);
        }
        __syncthreads();

        // Issue K/V tile 0 loads
        {
#pragma unroll
            for (int t = 0; t < 4; ++t) {
                int idx = tid + t * 256;
                int row = idx >> 4, c4 = (idx & 15) << 2;
                cp16(skb + (row * 68 + c4) * 4, kb + (size_t)row * DK_ + c4);
                cp16(svb + (row * 72 + c4) * 4, vb + (size_t)row * DK_ + c4);
            }
            cp_commit();
        }

        // Q fragments -> registers
        unsigned q[8][4];
#pragma unroll
        for (int ks = 0; ks < 8; ++ks) {
            int kb8 = ks * 8;
            q[ks][0] = sP[(w16 + g) * 68 + kb8 + tig];
            q[ks][1] = sP[(w16 + 8 + g) * 68 + kb8 + tig];
            q[ks][2] = sP[(w16 + g) * 68 + kb8 + tig + 4];
            q[ks][3] = sP[(w16 + 8 + g) * 68 + kb8 + tig + 4];
        }

        float m0 = -1e30f, m1 = -1e30f, l0 = 0.f, l1 = 0.f;
        float o[8][4];
#pragma unroll
        for (int nt = 0; nt < 8; ++nt)
#pragma unroll
            for (int i = 0; i < 4; ++i) o[nt][i] = 0.f;

        for (int kt = 0; kt <= kt_end; ++kt) {
            int s = kt & 1;
            if (kt < kt_end) {
                const unsigned* kn = kb + (size_t)(kt + 1) * 64 * DK_;
                const unsigned* vn = vb + (size_t)(kt + 1) * 64 * DK_;
                unsigned ka = skb + (s ^ 1) * KST * 4;
                unsigned va = svb + (s ^ 1) * VST * 4;
#pragma unroll
                for (int t = 0; t < 4; ++t) {
                    int idx = tid + t * 256;
                    int row = idx >> 4, c4 = (idx & 15) << 2;
                    cp16(ka + (row * 68 + c4) * 4, kn + (size_t)row * DK_ + c4);
                    cp16(va + (row * 72 + c4) * 4, vn + (size_t)row * DK_ + c4);
                }
                cp_commit();
                cp_wait1();
            } else {
                cp_wait0();
            }
            __syncthreads();

            const unsigned* cK = sK + s * KST;
            const unsigned* cV = sV + s * VST;

            // S = Q * K^T  (16x64 per warp)
            float sc[8][4];
#pragma unroll
            for (int nt = 0; nt < 8; ++nt)
#pragma unroll
                for (int i = 0; i < 4; ++i) sc[nt][i] = 0.f;

#pragma unroll
            for (int ks = 0; ks < 8; ++ks) {
                int kb8 = ks * 8;
#pragma unroll
                for (int nt = 0; nt < 8; ++nt) {
                    int n0 = nt * 8;
                    unsigned b0 = cK[(n0 + g) * 68 + kb8 + tig];
                    unsigned b1 = cK[(n0 + g) * 68 + kb8 + tig + 4];
                    mma_tf32(sc[nt], q[ks][0], q[ks][1], q[ks][2], q[ks][3], b0, b1);
                }
            }

            // Causal mask (partial tiles only)
            if (msk && kt >= 2 * qt) {
                int ra = qt * 128 + w16 + g;
                int rb = ra + 8;
#pragma unroll
                for (int nt = 0; nt < 8; ++nt) {
                    int c0 = kt * 64 + nt * 8 + tig * 2, c1 = c0 + 1;
                    if (c0 > ra) sc[nt][0] = -1e30f;
                    if (c1 > ra) sc[nt][1] = -1e30f;
                    if (c0 > rb) sc[nt][2] = -1e30f;
                    if (c1 > rb) sc[nt][3] = -1e30f;
                }
            }

            // Online softmax + P -> sP (tf32)
            {
                float mxa = -1e30f, mxb = -1e30f;
#pragma unroll
                for (int nt = 0; nt < 8; ++nt) {
                    mxa = fmaxf(mxa, fmaxf(sc[nt][0], sc[nt][1]));
                    mxb = fmaxf(mxb, fmaxf(sc[nt][2], sc[nt][3]));
                }
#pragma unroll
                for (int off = 1; off < 4; off <<= 1) {
                    mxa = fmaxf(mxa, __shfl_xor_sync(0xffffffffu, mxa, off));
                    mxb = fmaxf(mxb, __shfl_xor_sync(0xffffffffu, mxb, off));
                }
                float mna = fmaxf(m0, mxa), mnb = fmaxf(m1, mxb);
                float ala = __expf(m0 - mna), alb = __expf(m1 - mnb);
                float sa = 0.f, sb = 0.f;
#pragma unroll
                for (int nt = 0; nt < 8; ++nt) {
                    float p0 = __expf(sc[nt][0] - mna);
                    float p1 = __expf(sc[nt][1] - mna);
                    float p2 = __expf(sc[nt][2] - mnb);
                    float p3 = __expf(sc[nt][3] - mnb);
                    sa += p0 + p1; sb += p2 + p3;
                    uint2 ua; ua.x = f2tf(p0); ua.y = f2tf(p1);
                    uint2 ub; ub.x = f2tf(p2); ub.y = f2tf(p3);
                    *(uint2*)&sP[(w16 + g) * 68 + nt * 8 + tig * 2]     = ua;
                    *(uint2*)&sP[(w16 + 8 + g) * 68 + nt * 8 + tig * 2] = ub;
                }
#pragma unroll
                for (int off = 1; off < 4; off <<= 1) {
                    sa += __shfl_xor_sync(0xffffffffu, sa, off);
                    sb += __shfl_xor_sync(0xffffffffu, sb, off);
                }
                l0 = l0 * ala + sa; m0 = mna;
                l1 = l1 * alb + sb; m1 = mnb;
#pragma unroll
                for (int nt = 0; nt < 8; ++nt) {
                    o[nt][0] *= ala; o[nt][1] *= ala;
                    o[nt][2] *= alb; o[nt][3] *= alb;
                }
            }
            __syncwarp();   // warp's own sP rows only

            // O += P * V  (16x64 per warp)
#pragma unroll
            for (int ks = 0; ks < 8; ++ks) {
                int kb8 = ks * 8;
                unsigned pa0 = sP[(w16 + g) * 68 + kb8 + tig];
                unsigned pa1 = sP[(w16 + 8 + g) * 68 + kb8 + tig];
                unsigned pa2 = sP[(w16 + g) * 68 + kb8 + tig + 4];
                unsigned pa3 = sP[(w16 + 8 + g) * 68 + kb8 + tig + 4];
#pragma unroll
                for (int nt = 0; nt < 8; ++nt) {
                    int n0 = nt * 8;
                    unsigned b0 = cV[(kb8 + tig) * 72 + n0 + g];
                    unsigned b1 = cV[(kb8 + tig + 4) * 72 + n0 + g];
                    mma_tf32(o[nt], pa0, pa1, pa2, pa3, b0, b1);
                }
            }
            __syncthreads();   // all warps done with buffer s before refill
        }

        // Normalize + write tf32 to g_att [bn][h*64+col]
        float ia = 1.f / l0, ib = 1.f / l1;
        int na = qt * 128 + w16 + g;
        int nb = na + 8;
#pragma unroll
        for (int nt = 0; nt < 8; ++nt) {
            int col = h * 64 + nt * 8 + tig * 2;
            uint2 ua, ub;
            ua.x = f2tf(o[nt][0] * ia); ua.y = f2tf(o[nt][1] * ia);
            ub.x = f2tf(o[nt][2] * ib); ub.y = f2tf(o[nt][3] * ib);
            *(uint2*)&g_att[(size_t)(b * N_ + na) * DM_ + col] = ua;
            *(uint2*)&g_att[(size_t)(b * N_ + nb) * DM_ + col] = ub;
        }
    }
}

// ---------------------------------------------------------------------------
extern "C" void kernel_launch(void* const* d_in, const int* in_sizes, int n_in,
                              void* d_out, int out_size)
{
    const float* Q  = (const float*)d_in[0];
    const float* K  = (const float*)d_in[1];
    const float* V  = (const float*)d_in[2];
    const float* Wq = (const float*)d_in[3];
    const float* bq = (const float*)d_in[4];
    const float* Wk = (const float*)d_in[5];
    const float* bk = (const float*)d_in[6];
    const float* Wv = (const float*)d_in[7];
    const float* bv = (const float*)d_in[8];
    const float* Wo = (const float*)d_in[9];
    const float* bo = (const float*)d_in[10];
    const int*  msk = (const int*)d_in[11];
    float* out = (float*)d_out;

    cudaFuncSetAttribute(proj_gemm,    cudaFuncAttributeMaxDynamicSharedMemorySize, GEMM_SMEM);
    cudaFuncSetAttribute(outproj_gemm, cudaFuncAttributeMaxDynamicSharedMemorySize, GEMM_SMEM);
    cudaFuncSetAttribute(flash_kernel, cudaFuncAttributeMaxDynamicSharedMemorySize, FL_SMEM);

    cvt_w_kernel<<<dim3(4096, 3), 256>>>(Wq, Wk, Wv);
    cvt_wo_kernel<<<1024, 256>>>(Wo);
    proj_gemm<<<dim3(8, 64, 3), 256, GEMM_SMEM>>>(Q, K, V, bq, bk, bv);
    flash_kernel<<<dim3(8, H_, B_), 256, FL_SMEM>>>(msk);
    outproj_gemm<<<dim3(8, 64), 256, GEMM_SMEM>>>(bo, out);
}

// round 11
// speedup vs baseline: 1.1165x; 1.0256x over previous
#include <cuda_runtime.h>

#define B_  4
#define N_  2048
#define H_  16
#define DM_ 1024
#define DK_ 64
#define BN_ (B_*N_)          // 8192

// ---------------- scratch (device globals; no allocation allowed) ----------
__device__ unsigned g_wT[3][DM_*DM_];    // tf32 proj weights, [n=h*64+j][k]
__device__ unsigned g_woT[DM_*DM_];      // tf32 Wo transposed, [n][k]
__device__ unsigned g_q[B_*H_*N_*DK_];   // tf32, [b,h,n,dk] (pre-scaled by 0.125)
__device__ unsigned g_k[B_*H_*N_*DK_];
__device__ unsigned g_v[B_*H_*N_*DK_];
__device__ unsigned g_att[BN_*DM_];      // tf32 attention output [bn][h*dv]

__device__ __forceinline__ unsigned f2tf(float x) {
    unsigned r;
    asm("cvt.rna.tf32.f32 %0, %1;" : "=r"(r) : "f"(x));
    return r;
}

__device__ __forceinline__ void mma_tf32(float c[4],
    unsigned a0, unsigned a1, unsigned a2, unsigned a3,
    unsigned b0, unsigned b1)
{
    asm("mma.sync.aligned.m16n8k8.row.col.f32.tf32.tf32.f32 "
        "{%0,%1,%2,%3},{%4,%5,%6,%7},{%8,%9},{%0,%1,%2,%3};"
        : "+f"(c[0]), "+f"(c[1]), "+f"(c[2]), "+f"(c[3])
        : "r"(a0), "r"(a1), "r"(a2), "r"(a3), "r"(b0), "r"(b1));
}

#define LDSM4(r0, r1, r2, r3, addr) \
    asm volatile("ldmatrix.sync.aligned.m8n8.x4.shared.b16 {%0,%1,%2,%3}, [%4];" \
        : "=r"(r0), "=r"(r1), "=r"(r2), "=r"(r3) : "r"(addr))

__device__ __forceinline__ void cp16(unsigned d, const void* s) {
    asm volatile("cp.async.cg.shared.global [%0], [%1], 16;" :: "r"(d), "l"(s));
}
__device__ __forceinline__ void cp_commit() { asm volatile("cp.async.commit_group;"); }
__device__ __forceinline__ void cp_wait1()  { asm volatile("cp.async.wait_group 1;"); }
__device__ __forceinline__ void cp_wait0()  { asm volatile("cp.async.wait_group 0;"); }

// ---------------------------------------------------------------------------
// Weight conversion + transpose kernels (fp32 -> tf32 bits, [n][k] layout)
// ---------------------------------------------------------------------------
// Wq/Wk/Wv [h][k][j] -> g_wT [n=h*64+j][k]
__global__ void cvt_wT_kernel(const float* __restrict__ Wq,
                              const float* __restrict__ Wk,
                              const float* __restrict__ Wv)
{
    __shared__ float t[32][33];
    int op = blockIdx.z >> 4, h = blockIdx.z & 15;
    const float* w = ((op == 0) ? Wq : (op == 1) ? Wk : Wv) + (size_t)h * DM_ * DK_;
    unsigned* dst = g_wT[op];
    int k0 = blockIdx.x * 32, j0 = blockIdx.y * 32;
    int tx = threadIdx.x, ty = threadIdx.y;
#pragma unroll
    for (int i = 0; i < 4; ++i)
        t[ty + i * 8][tx] = w[(size_t)(k0 + ty + i * 8) * DK_ + j0 + tx];
    __syncthreads();
#pragma unroll
    for (int i = 0; i < 4; ++i)
        dst[(size_t)(h * 64 + j0 + ty + i * 8) * DM_ + k0 + tx] = f2tf(t[tx][ty + i * 8]);
}

// Wo [k][n] -> g_woT [n][k]
__global__ void cvt_woT_kernel(const float* __restrict__ Wo)
{
    __shared__ float t[32][33];
    int k0 = blockIdx.x * 32, n0 = blockIdx.y * 32;
    int tx = threadIdx.x, ty = threadIdx.y;
#pragma unroll
    for (int i = 0; i < 4; ++i)
        t[ty + i * 8][tx] = Wo[(size_t)(k0 + ty + i * 8) * DM_ + n0 + tx];
    __syncthreads();
#pragma unroll
    for (int i = 0; i < 4; ++i)
        g_woT[(size_t)(n0 + ty + i * 8) * DM_ + k0 + tx] = f2tf(t[tx][ty + i * 8]);
}

// ---------------------------------------------------------------------------
// 128x128 tf32 GEMM, BK=32, 8 warps (32x64 warp tiles), cp.async 2-stage,
// ldmatrix fragment loads. A: [128 m][1024 k]. B: [128 n][1024 k] (transposed
// weights). Both stage tiles are [128 rows][36 words].
// ---------------------------------------------------------------------------
#define AST 4608                    // 128*36 words per A stage
#define BST 4608                    // 128*36 words per B stage
#define GEMM_SMEM ((AST + BST) * 2 * 4)   // 73728 B

struct GemmAcc { float a[2][8][4]; };

template<bool CVTA>
__device__ __forceinline__ void gemm_mainloop(
    const unsigned* __restrict__ A,     // block-row base, ld = DM_
    const unsigned* __restrict__ Bw,    // n-row base (transposed W), ld = DM_
    unsigned* sA, unsigned* sB, GemmAcc& acc)
{
    const int tid  = threadIdx.x;
    const int wid  = tid >> 5, lane = tid & 31;
    const int wm   = wid & 3;          // rows wm*32
    const int wn   = wid >> 2;         // cols wn*64
    const int lm   = lane >> 3;        // ldsm matrix id 0..3
    const int lr   = lane & 7;         // row within matrix

    const unsigned abase = (unsigned)__cvta_generic_to_shared(sA);
    const unsigned bbase = (unsigned)__cvta_generic_to_shared(sB);

    // LDSM base offsets (bytes) within a stage; lm&1 -> row block, lm>>1 -> k half
    unsigned aoff[2], boff[4];
#pragma unroll
    for (int mt = 0; mt < 2; ++mt)
        aoff[mt] = ((wm*32 + mt*16 + ((lm & 1) << 3) + lr) * 36 + ((lm >> 1) << 2)) * 4;
#pragma unroll
    for (int p = 0; p < 4; ++p)
        boff[p] = ((wn*64 + p*16 + ((lm & 1) << 3) + lr) * 36 + ((lm >> 1) << 2)) * 4;

#pragma unroll
    for (int mt = 0; mt < 2; ++mt)
#pragma unroll
        for (int nt = 0; nt < 8; ++nt)
#pragma unroll
            for (int i = 0; i < 4; ++i) acc.a[mt][nt][i] = 0.f;

    // prologue: stage 0
    {
#pragma unroll
        for (int t = 0; t < 4; ++t) {
            int ca = tid + t * 256;
            int row = ca >> 3, cc = ca & 7;
            cp16(abase + (row * 36 + cc * 4) * 4, A + (size_t)row * DM_ + cc * 4);
            cp16(bbase + (row * 36 + cc * 4) * 4, Bw + (size_t)row * DM_ + cc * 4);
        }
        cp_commit();
    }

    for (int kt = 0; kt < 32; ++kt) {
        int s = kt & 1;
        if (kt < 31) {
            int k0 = (kt + 1) * 32;
            unsigned ab = abase + (s ^ 1) * AST * 4;
            unsigned bb = bbase + (s ^ 1) * BST * 4;
#pragma unroll
            for (int t = 0; t < 4; ++t) {
                int ca = tid + t * 256;
                int row = ca >> 3, cc = ca & 7;
                cp16(ab + (row * 36 + cc * 4) * 4, A + (size_t)row * DM_ + k0 + cc * 4);
                cp16(bb + (row * 36 + cc * 4) * 4, Bw + (size_t)row * DM_ + k0 + cc * 4);
            }
            cp_commit();
            cp_wait1();
        } else {
            cp_wait0();
        }
        __syncthreads();

        unsigned sa = abase + s * AST * 4;
        unsigned sb = bbase + s * BST * 4;
#pragma unroll
        for (int ks = 0; ks < 4; ++ks) {
            unsigned koff = ks * 32;           // 8 words = 32 bytes
            unsigned a[2][4], bf[8][2];
#pragma unroll
            for (int mt = 0; mt < 2; ++mt) {
                LDSM4(a[mt][0], a[mt][1], a[mt][2], a[mt][3], sa + aoff[mt] + koff);
                if (CVTA) {
                    a[mt][0] = f2tf(__uint_as_float(a[mt][0]));
                    a[mt][1] = f2tf(__uint_as_float(a[mt][1]));
                    a[mt][2] = f2tf(__uint_as_float(a[mt][2]));
                    a[mt][3] = f2tf(__uint_as_float(a[mt][3]));
                }
            }
            // r0 = rows 0-7 k0-3 (b0, nt=2p); r1 = rows 8-15 k0-3 (b0, nt=2p+1)
            // r2 = rows 0-7 k4-7 (b1, nt=2p); r3 = rows 8-15 k4-7 (b1, nt=2p+1)
#pragma unroll
            for (int p = 0; p < 4; ++p)
                LDSM4(bf[2*p][0], bf[2*p+1][0], bf[2*p][1], bf[2*p+1][1],
                      sb + boff[p] + koff);
#pragma unroll
            for (int mt = 0; mt < 2; ++mt)
#pragma unroll
                for (int nt = 0; nt < 8; ++nt)
                    mma_tf32(acc.a[mt][nt], a[mt][0], a[mt][1], a[mt][2], a[mt][3],
                             bf[nt][0], bf[nt][1]);
        }
        __syncthreads();
    }
}

// ---------------------------------------------------------------------------
// Projections: grid (8, 64, 3), 256 threads. Raw fp32 A inputs. C -> tf32.
// ---------------------------------------------------------------------------
__global__ __launch_bounds__(256, 2) void proj_gemm(
    const float* __restrict__ Qp, const float* __restrict__ Kp,
    const float* __restrict__ Vp,
    const float* __restrict__ bq, const float* __restrict__ bk,
    const float* __restrict__ bv)
{
    extern __shared__ unsigned sm[];
    unsigned* sA = sm;
    unsigned* sB = sm + 2 * AST;

    const int op = blockIdx.z;
    const float* Xp = (op == 0) ? Qp : (op == 1) ? Kp : Vp;
    const unsigned* A  = (const unsigned*)Xp + (size_t)blockIdx.y * 128 * DM_;
    const unsigned* Bw = g_wT[op] + (size_t)blockIdx.x * 128 * DM_;
    const float* bias  = (op == 0) ? bq : (op == 1) ? bk : bv;
    unsigned* dst      = (op == 0) ? g_q : (op == 1) ? g_k : g_v;
    const float scale  = (op == 0) ? 0.125f : 1.f;

    GemmAcc acc;
    gemm_mainloop<true>(A, Bw, sA, sB, acc);

    const int tid = threadIdx.x, wid = tid >> 5, lane = tid & 31;
    const int g = lane >> 2, tig = lane & 3;
    const int wm = wid & 3, wn = wid >> 2;

#pragma unroll
    for (int mt = 0; mt < 2; ++mt) {
#pragma unroll
        for (int nt = 0; nt < 8; ++nt) {
#pragma unroll
            for (int half = 0; half < 2; ++half) {
                int r  = wm * 32 + mt * 16 + half * 8 + g;
                int c  = wn * 64 + nt * 8 + tig * 2;
                int rg = blockIdx.y * 128 + r;
                int cg = blockIdx.x * 128 + c;
                int b  = rg >> 11, n = rg & 2047;
                int h  = cg >> 6,  j = cg & 63;
                float v0 = (acc.a[mt][nt][half * 2 + 0] + bias[cg]) * scale;
                float v1 = (acc.a[mt][nt][half * 2 + 1] + bias[cg + 1]) * scale;
                uint2 u; u.x = f2tf(v0); u.y = f2tf(v1);
                *(uint2*)&dst[(size_t)(((b << 4) | h) * N_ + n) * DK_ + j] = u;
            }
        }
    }
}

// ---------------------------------------------------------------------------
// Output projection: grid (8, 64), 256 threads. C -> fp32 out.
// ---------------------------------------------------------------------------
__global__ __launch_bounds__(256, 2) void outproj_gemm(
    const float* __restrict__ bo, float* __restrict__ out)
{
    extern __shared__ unsigned sm[];
    unsigned* sA = sm;
    unsigned* sB = sm + 2 * AST;

    const unsigned* A  = g_att + (size_t)blockIdx.y * 128 * DM_;
    const unsigned* Bw = g_woT + (size_t)blockIdx.x * 128 * DM_;

    GemmAcc acc;
    gemm_mainloop<false>(A, Bw, sA, sB, acc);

    const int tid = threadIdx.x, wid = tid >> 5, lane = tid & 31;
    const int g = lane >> 2, tig = lane & 3;
    const int wm = wid & 3, wn = wid >> 2;

#pragma unroll
    for (int mt = 0; mt < 2; ++mt) {
#pragma unroll
        for (int nt = 0; nt < 8; ++nt) {
#pragma unroll
            for (int half = 0; half < 2; ++half) {
                int r  = wm * 32 + mt * 16 + half * 8 + g;
                int c  = wn * 64 + nt * 8 + tig * 2;
                int rg = blockIdx.y * 128 + r;
                int cg = blockIdx.x * 128 + c;
                float2 v;
                v.x = acc.a[mt][nt][half * 2 + 0] + bo[cg];
                v.y = acc.a[mt][nt][half * 2 + 1] + bo[cg + 1];
                *(float2*)(out + (size_t)rg * DM_ + cg) = v;
            }
        }
    }
}

// ---------------------------------------------------------------------------
// Flash attention: grid (8, 16, 4), 256 threads (8 warps x 16 q-rows).
// Work pairing {bx, 15-bx}; ldmatrix for Q/K/P fragments; 2 CTAs/SM.
// ---------------------------------------------------------------------------
#define KST (64*68)     // K stage words
#define VST (64*72)     // V stage words
#define FL_SMEM ((2*KST + 2*VST + 128*68) * 4)   // 106.5 KB

__global__ __launch_bounds__(256, 2) void flash_kernel(const int* __restrict__ mask_ptr)
{
    extern __shared__ unsigned sm[];
    unsigned* sK = sm;                        // [2][64][68]
    unsigned* sV = sm + 2 * KST;              // [2][64][72]
    unsigned* sP = sm + 2 * KST + 2 * VST;    // [128][68]

    const int tid = threadIdx.x, wid = tid >> 5, lane = tid & 31;
    const int g = lane >> 2, tig = lane & 3;
    const int lm = lane >> 3, lr = lane & 7;
    const int bx = blockIdx.x, h = blockIdx.y, b = blockIdx.z;
    const int bh = b * H_ + h;
    const unsigned* qb = g_q + (size_t)bh * N_ * DK_;
    const unsigned* kb = g_k + (size_t)bh * N_ * DK_;
    const unsigned* vb = g_v + (size_t)bh * N_ * DK_;
    const int w16 = wid * 16;

    const unsigned skb = (unsigned)__cvta_generic_to_shared(sK);
    const unsigned svb = (unsigned)__cvta_generic_to_shared(sV);
    const unsigned spb = (unsigned)__cvta_generic_to_shared(sP);

    // LDSM offsets: K frags (lm>>1 -> row block, lm&1 -> k half);
    // P/Q frags (lm&1 -> row block, lm>>1 -> k half)
    unsigned koff[4];
#pragma unroll
    for (int p = 0; p < 4; ++p)
        koff[p] = ((p*16 + ((lm >> 1) << 3) + lr) * 68 + ((lm & 1) << 2)) * 4;
    const unsigned poff = spb + ((w16 + ((lm & 1) << 3) + lr) * 68 + ((lm >> 1) << 2)) * 4;

    const int msk = *mask_ptr;

    for (int pass = 0; pass < 2; ++pass) {
        const int qt = pass ? (15 - bx) : bx;
        const int kt_end = msk ? (2 * qt + 1) : (N_ / 64 - 1);

        // Stage Q tile (128x64) into sP
#pragma unroll
        for (int t = 0; t < 8; ++t) {
            int idx = tid + t * 256;
            int row = idx >> 4, c4 = (idx & 15) << 2;
            *(uint4*)&sP[row * 68 + c4] =
                *(const uint4*)(qb + (size_t)(qt * 128 + row) * DK_ + c4);
        }
        __syncthreads();

        // Issue K/V tile 0 loads
        {
#pragma unroll
            for (int t = 0; t < 4; ++t) {
                int idx = tid + t * 256;
                int row = idx >> 4, c4 = (idx & 15) << 2;
                cp16(skb + (row * 68 + c4) * 4, kb + (size_t)row * DK_ + c4);
                cp16(svb + (row * 72 + c4) * 4, vb + (size_t)row * DK_ + c4);
            }
            cp_commit();
        }

        // Q fragments -> registers (via LDSM)
        unsigned q[8][4];
#pragma unroll
        for (int ks = 0; ks < 8; ++ks)
            LDSM4(q[ks][0], q[ks][1], q[ks][2], q[ks][3], poff + ks * 32);

        float m0 = -1e30f, m1 = -1e30f, l0 = 0.f, l1 = 0.f;
        float o[8][4];
#pragma unroll
        for (int nt = 0; nt < 8; ++nt)
#pragma unroll
            for (int i = 0; i < 4; ++i) o[nt][i] = 0.f;

        for (int kt = 0; kt <= kt_end; ++kt) {
            int s = kt & 1;
            if (kt < kt_end) {
                const unsigned* kn = kb + (size_t)(kt + 1) * 64 * DK_;
                const unsigned* vn = vb + (size_t)(kt + 1) * 64 * DK_;
                unsigned ka = skb + (s ^ 1) * KST * 4;
                unsigned va = svb + (s ^ 1) * VST * 4;
#pragma unroll
                for (int t = 0; t < 4; ++t) {
                    int idx = tid + t * 256;
                    int row = idx >> 4, c4 = (idx & 15) << 2;
                    cp16(ka + (row * 68 + c4) * 4, kn + (size_t)row * DK_ + c4);
                    cp16(va + (row * 72 + c4) * 4, vn + (size_t)row * DK_ + c4);
                }
                cp_commit();
                cp_wait1();
            } else {
                cp_wait0();
            }
            __syncthreads();

            const unsigned cKa = skb + s * KST * 4;
            const unsigned* cV = sV + s * VST;

            // S = Q * K^T  (16x64 per warp), K frags via LDSM
            float sc[8][4];
#pragma unroll
            for (int nt = 0; nt < 8; ++nt)
#pragma unroll
                for (int i = 0; i < 4; ++i) sc[nt][i] = 0.f;

#pragma unroll
            for (int ks = 0; ks < 8; ++ks) {
                unsigned kof = ks * 32;
#pragma unroll
                for (int p = 0; p < 4; ++p) {
                    unsigned k0r, k1r, k2r, k3r;
                    LDSM4(k0r, k1r, k2r, k3r, cKa + koff[p] + kof);
                    mma_tf32(sc[2*p],   q[ks][0], q[ks][1], q[ks][2], q[ks][3], k0r, k1r);
                    mma_tf32(sc[2*p+1], q[ks][0], q[ks][1], q[ks][2], q[ks][3], k2r, k3r);
                }
            }

            // Causal mask (partial tiles only)
            if (msk && kt >= 2 * qt) {
                int ra = qt * 128 + w16 + g;
                int rb = ra + 8;
#pragma unroll
                for (int nt = 0; nt < 8; ++nt) {
                    int c0 = kt * 64 + nt * 8 + tig * 2, c1 = c0 + 1;
                    if (c0 > ra) sc[nt][0] = -1e30f;
                    if (c1 > ra) sc[nt][1] = -1e30f;
                    if (c0 > rb) sc[nt][2] = -1e30f;
                    if (c1 > rb) sc[nt][3] = -1e30f;
                }
            }

            // Online softmax + P -> sP (tf32)
            {
                float mxa = -1e30f, mxb = -1e30f;
#pragma unroll
                for (int nt = 0; nt < 8; ++nt) {
                    mxa = fmaxf(mxa, fmaxf(sc[nt][0], sc[nt][1]));
                    mxb = fmaxf(mxb, fmaxf(sc[nt][2], sc[nt][3]));
                }
#pragma unroll
                for (int off = 1; off < 4; off <<= 1) {
                    mxa = fmaxf(mxa, __shfl_xor_sync(0xffffffffu, mxa, off));
                    mxb = fmaxf(mxb, __shfl_xor_sync(0xffffffffu, mxb, off));
                }
                float mna = fmaxf(m0, mxa), mnb = fmaxf(m1, mxb);
                float ala = __expf(m0 - mna), alb = __expf(m1 - mnb);
                float sa = 0.f, sb = 0.f;
#pragma unroll
                for (int nt = 0; nt < 8; ++nt) {
                    float p0 = __expf(sc[nt][0] - mna);
                    float p1 = __expf(sc[nt][1] - mna);
                    float p2 = __expf(sc[nt][2] - mnb);
                    float p3 = __expf(sc[nt][3] - mnb);
                    sa += p0 + p1; sb += p2 + p3;
                    uint2 ua; ua.x = f2tf(p0); ua.y = f2tf(p1);
                    uint2 ub; ub.x = f2tf(p2); ub.y = f2tf(p3);
                    *(uint2*)&sP[(w16 + g) * 68 + nt * 8 + tig * 2]     = ua;
                    *(uint2*)&sP[(w16 + 8 + g) * 68 + nt * 8 + tig * 2] = ub;
                }
#pragma unroll
                for (int off = 1; off < 4; off <<= 1) {
                    sa += __shfl_xor_sync(0xffffffffu, sa, off);
                    sb += __shfl_xor_sync(0xffffffffu, sb, off);
                }
                l0 = l0 * ala + sa; m0 = mna;
                l1 = l1 * alb + sb; m1 = mnb;
#pragma unroll
                for (int nt = 0; nt < 8; ++nt) {
                    o[nt][0] *= ala; o[nt][1] *= ala;
                    o[nt][2] *= alb; o[nt][3] *= alb;
                }
            }
            __syncwarp();   // warp's own sP rows only

            // O += P * V  (16x64 per warp), P frags via LDSM
#pragma unroll
            for (int ks = 0; ks < 8; ++ks) {
                int kb8 = ks * 8;
                unsigned pa0, pa1, pa2, pa3;
                LDSM4(pa0, pa1, pa2, pa3, poff + ks * 32);
#pragma unroll
                for (int nt = 0; nt < 8; ++nt) {
                    int n0 = nt * 8;
                    unsigned b0 = cV[(kb8 + tig) * 72 + n0 + g];
                    unsigned b1 = cV[(kb8 + tig + 4) * 72 + n0 + g];
                    mma_tf32(o[nt], pa0, pa1, pa2, pa3, b0, b1);
                }
            }
            __syncthreads();   // all warps done with buffer s before refill
        }

        // Normalize + write tf32 to g_att [bn][h*64+col]
        float ia = 1.f / l0, ib = 1.f / l1;
        int na = qt * 128 + w16 + g;
        int nb = na + 8;
#pragma unroll
        for (int nt = 0; nt < 8; ++nt) {
            int col = h * 64 + nt * 8 + tig * 2;
            uint2 ua, ub;
            ua.x = f2tf(o[nt][0] * ia); ua.y = f2tf(o[nt][1] * ia);
            ub.x = f2tf(o[nt][2] * ib); ub.y = f2tf(o[nt][3] * ib);
            *(uint2*)&g_att[(size_t)(b * N_ + na) * DM_ + col] = ua;
            *(uint2*)&g_att[(size_t)(b * N_ + nb) * DM_ + col] = ub;
        }
    }
}

// ---------------------------------------------------------------------------
extern "C" void kernel_launch(void* const* d_in, const int* in_sizes, int n_in,
                              void* d_out, int out_size)
{
    const float* Q  = (const float*)d_in[0];
    const float* K  = (const float*)d_in[1];
    const float* V  = (const float*)d_in[2];
    const float* Wq = (const float*)d_in[3];
    const float* bq = (const float*)d_in[4];
    const float* Wk = (const float*)d_in[5];
    const float* bk = (const float*)d_in[6];
    const float* Wv = (const float*)d_in[7];
    const float* bv = (const float*)d_in[8];
    const float* Wo = (const float*)d_in[9];
    const float* bo = (const float*)d_in[10];
    const int*  msk = (const int*)d_in[11];
    float* out = (float*)d_out;

    cudaFuncSetAttribute(proj_gemm,    cudaFuncAttributeMaxDynamicSharedMemorySize, GEMM_SMEM);
    cudaFuncSetAttribute(outproj_gemm, cudaFuncAttributeMaxDynamicSharedMemorySize, GEMM_SMEM);
    cudaFuncSetAttribute(flash_kernel, cudaFuncAttributeMaxDynamicSharedMemorySize, FL_SMEM);

    cvt_wT_kernel<<<dim3(32, 2, 48), dim3(32, 8)>>>(Wq, Wk, Wv);
    cvt_woT_kernel<<<dim3(32, 32), dim3(32, 8)>>>(Wo);
    proj_gemm<<<dim3(8, 64, 3), 256, GEMM_SMEM>>>(Q, K, V, bq, bk, bv);
    flash_kernel<<<dim3(8, H_, B_), 256, FL_SMEM>>>(msk);
    outproj_gemm<<<dim3(8, 64), 256, GEMM_SMEM>>>(bo, out);
}